// round 13
// baseline (speedup 1.0000x reference)
#include <cuda_runtime.h>
#include <cuda_fp16.h>
#include <cstdint>

// Problem constants (fixed by setup_inputs)
#define BWIN   4096
#define NTOK   49
#define CDIM   256
#define NHEAD  8
#define MROWS  (BWIN * NTOK)   // 200704

// ---------------------------------------------------------------------------
// Scratch (device globals; no runtime allocation allowed)
// ---------------------------------------------------------------------------
__device__ __half   g_qkv[(size_t)MROWS * 768];
__device__ __half   g_att[(size_t)MROWS * CDIM];
__device__ uint32_t g_wqkv[6 * 16 * 32 * 32];        // lane-major frag fp16 words
__device__ uint32_t g_wproj[2 * 16 * 32 * 32];
__device__ uint32_t g_bias[NHEAD * 64 * 32];         // [h][i][t][8] half2 words

__device__ __forceinline__ uint32_t pack_h2(float a, float b) {
    __half2 h = __floats2half2_rn(a, b);
    return *(uint32_t*)&h;
}

// ---------------------------------------------------------------------------
// Weight conversion: fp32 W[K,N] -> lane-major fragment words:
//   dst[((nblk*16 + kc)*32 + lane)*32 + w],  w = wn*16 + nt*2 + reg
//   lane = g*4 + t;  n = nblk*128 + wn*64 + nt*8 + g;  k = kc*16 + reg*8 + t*2
//   word = half2(W[k][n], W[k+1][n])
// In the GEMM each thread reads its 16 words per kc as 4x LDG.128.
// ---------------------------------------------------------------------------
__global__ void convert_w(const float* __restrict__ w, uint32_t* __restrict__ dst, int N)
{
    const int idx  = blockIdx.x * 256 + threadIdx.x;
    const int wrd  = idx & 31;
    const int lane = (idx >> 5) & 31;
    const int kc   = (idx >> 10) & 15;
    const int nblk = idx >> 14;
    const int wn  = wrd >> 4;
    const int nt  = (wrd >> 1) & 7;
    const int reg = wrd & 1;
    const int g = lane >> 2, t = lane & 3;
    const int n = nblk * 128 + wn * 64 + nt * 8 + g;
    const int k = kc * 16 + reg * 8 + t * 2;
    dst[idx] = pack_h2(w[(size_t)k * N + n], w[(size_t)(k + 1) * N + n]);
}

// ---------------------------------------------------------------------------
// Bias+mask table: g_bias[((h*64+i)*4 + t)*8 + nt] = half2(B(i,j), B(i,j+1))
// ---------------------------------------------------------------------------
__global__ void build_bias(const float* __restrict__ rpb, uint32_t* __restrict__ dst)
{
    const int idx = blockIdx.x * 256 + threadIdx.x;
    const int nt = idx & 7;
    const int t  = (idx >> 3) & 3;
    const int i  = (idx >> 5) & 63;
    const int h  = idx >> 11;
    const int j0 = nt * 8 + 2 * t;
    float v[2];
#pragma unroll
    for (int e = 0; e < 2; e++) {
        const int j = j0 + e;
        if (i < NTOK && j < NTOK && nt < 7) {
            const int xi = i / 7, yi = i - xi * 7;
            const int xj = j / 7, yj = j - xj * 7;
            v[e] = rpb[((xi - xj + 6) * 13 + (yi - yj + 6)) * 8 + h];
        } else {
            v[e] = -10000.0f;
        }
    }
    dst[idx] = pack_h2(v[0], v[1]);
}

// ---------------------------------------------------------------------------
// BARRIER-FREE A-resident fp16 GEMM (r11 structure) + LDG.128 B loads.
// BM=128, 4 warps, 2 CTA/SM. A fragment image resident in 64KB smem (one
// sync). B frags: 4x LDG.128 per thread per kc from lane-major gmem layout,
// consumed directly — no staging registers, no spill risk, same reg count
// as r11. The unrolled loop lets the scoreboard hoist the wide loads.
// ---------------------------------------------------------------------------
template<typename TA, typename TC, int N>
__global__ __launch_bounds__(128, 2)
void h16_gemm(const TA* __restrict__ A, const uint32_t* __restrict__ Bw,
              const float* __restrict__ bias, TC* __restrict__ C)
{
    constexpr int K = 256, NT = 16, NBLK = N / 128;
    extern __shared__ uint32_t Asm[];     // 16 kc * 8 mt * 4 reg * 32 = 16384 words

    const int tid  = threadIdx.x;
    const int lane = tid & 31;
    const int warp = tid >> 5;
    const int wm   = warp & 1;
    const int wn   = warp >> 1;
    const int bm   = blockIdx.x * 128;

    // ---- A resident fill (once) ---------------------------------------------
    if constexpr (sizeof(TA) == 4) {
#pragma unroll
        for (int it = 0; it < 64; it++) {
            const int e = it * 128 + tid;
            const int row = e >> 6, c4 = e & 63;
            const int k = c4 * 4;
            const int kc = k >> 4;
            const int reg = ((row >> 3) & 1) + ((k >> 3) & 1) * 2;
            const int t0 = (k & 7) >> 1;
            const int mt = (row >> 4);
            const int g = row & 7;
            float4 v = *(const float4*)((const float*)A + (size_t)(bm + row) * K + k);
            uint2 w;
            w.x = pack_h2(v.x, v.y);
            w.y = pack_h2(v.z, v.w);
            *(uint2*)&Asm[((kc * 8 + mt) * 4 + reg) * 32 + g * 4 + t0] = w;
        }
    } else {
#pragma unroll
        for (int it = 0; it < 32; it++) {
            const int e = it * 128 + tid;
            const int row = e >> 5, c8 = e & 31;
            const int k = c8 * 8;
            const int kc = k >> 4;
            const int reg = ((row >> 3) & 1) + ((k >> 3) & 1) * 2;
            const int mt = (row >> 4);
            const int g = row & 7;
            uint4 v = *(const uint4*)((const __half*)A + (size_t)(bm + row) * K + k);
            *(uint4*)&Asm[((kc * 8 + mt) * 4 + reg) * 32 + g * 4] = v;
        }
    }
    __syncthreads();    // the ONLY block-wide barrier

    float acc[4][8][4];

    for (int nblk = 0; nblk < NBLK; nblk++) {
#pragma unroll
        for (int i = 0; i < 4; i++)
#pragma unroll
            for (int j = 0; j < 8; j++)
#pragma unroll
                for (int r = 0; r < 4; r++) acc[i][j][r] = 0.f;

        // this thread's lane-major B stream: 16 contiguous words per kc
        const uint4* bwp = (const uint4*)(Bw + ((size_t)nblk * 16 * 32) * 32
                                             + lane * 32 + wn * 16);

#pragma unroll
        for (int kc = 0; kc < NT; kc++) {
            // B fragments: 4 wide coalesced loads, consumed in place
            uint32_t bf[16];
            const uint4* p = bwp + kc * 256;     // 1024 words / 4 per kc
            *(uint4*)&bf[0]  = __ldg(p + 0);
            *(uint4*)&bf[4]  = __ldg(p + 1);
            *(uint4*)&bf[8]  = __ldg(p + 2);
            *(uint4*)&bf[12] = __ldg(p + 3);

            // A fragments from resident smem (conflict-free LDS.32)
            uint32_t af[4][4];
#pragma unroll
            for (int mt = 0; mt < 4; mt++) {
                const int base = ((kc * 8 + wm * 4 + mt) * 4) * 32 + lane;
#pragma unroll
                for (int r = 0; r < 4; r++) af[mt][r] = Asm[base + r * 32];
            }
#pragma unroll
            for (int mt = 0; mt < 4; mt++) {
#pragma unroll
                for (int nt = 0; nt < 8; nt++) {
                    asm volatile(
                        "mma.sync.aligned.m16n8k16.row.col.f32.f16.f16.f32 "
                        "{%0,%1,%2,%3}, {%4,%5,%6,%7}, {%8,%9}, {%0,%1,%2,%3};"
                        : "+f"(acc[mt][nt][0]), "+f"(acc[mt][nt][1]),
                          "+f"(acc[mt][nt][2]), "+f"(acc[mt][nt][3])
                        : "r"(af[mt][0]), "r"(af[mt][1]), "r"(af[mt][2]), "r"(af[mt][3]),
                          "r"(bf[nt * 2]), "r"(bf[nt * 2 + 1]));
                }
            }
        }

        // epilogue: bias + store
        const int g = lane >> 2, tig = lane & 3;
#pragma unroll
        for (int mt = 0; mt < 4; mt++) {
            const int r0 = bm + wm * 64 + mt * 16 + g;
#pragma unroll
            for (int nt = 0; nt < 8; nt++) {
                const int col = nblk * 128 + wn * 64 + nt * 8 + tig * 2;
                const float b0 = __ldg(bias + col);
                const float b1 = __ldg(bias + col + 1);
                if constexpr (sizeof(TC) == 2) {
                    __half* cp = (__half*)C;
                    *(__half2*)(cp + (size_t)r0 * N + col) =
                        __floats2half2_rn(acc[mt][nt][0] + b0, acc[mt][nt][1] + b1);
                    *(__half2*)(cp + (size_t)(r0 + 8) * N + col) =
                        __floats2half2_rn(acc[mt][nt][2] + b0, acc[mt][nt][3] + b1);
                } else {
                    float* cp = (float*)C;
                    *(float2*)(cp + (size_t)r0 * N + col) =
                        make_float2(acc[mt][nt][0] + b0, acc[mt][nt][1] + b1);
                    *(float2*)(cp + (size_t)(r0 + 8) * N + col) =
                        make_float2(acc[mt][nt][2] + b0, acc[mt][nt][3] + b1);
                }
            }
        }
    }
}

// ---------------------------------------------------------------------------
// PURE fp16 tensor-core windowed attention (mma.sync), vectorized bias table.
// (unchanged from rounds 10-12)
// ---------------------------------------------------------------------------
__global__ __launch_bounds__(128)
void window_attn_h16(const __half* __restrict__ qkv,
                     const uint32_t* __restrict__ biasT,
                     __half* __restrict__ out)
{
    __shared__ uint32_t sq [64 * 36];
    __shared__ uint32_t sk [56 * 36];
    __shared__ uint32_t svT[32 * 36];
    __shared__ uint32_t sp [64 * 36];

    const int b = blockIdx.x;
    const int h = blockIdx.y;
    const int tid  = threadIdx.x;
    const int lane = tid & 31;
    const int warp = tid >> 5;
    const int g = lane >> 2;
    const int t = lane & 3;

    const float scale = 0.17677669529663687f;
    const __half* base = qkv + (size_t)b * NTOK * 768 + h * 32;

#pragma unroll
    for (int it = 0; it < 2; it++) {
        const int e = tid + it * 128;
        const int row = e >> 2, c = e & 3;
        const int sr = row < NTOK ? row : NTOK - 1;
        *(uint4*)&sq[row * 36 + c * 4] =
            *(const uint4*)(base + (size_t)sr * 768 + c * 8);
    }
#pragma unroll
    for (int it = 0; it < 2; it++) {
        const int e = tid + it * 128;
        if (e < 224) {
            const int row = e >> 2, c = e & 3;
            const int sr = row < NTOK ? row : NTOK - 1;
            *(uint4*)&sk[row * 36 + c * 4] =
                *(const uint4*)(base + (size_t)sr * 768 + 256 + c * 8);
        }
    }
    if (tid < 112) {
        const int tp = tid >> 2, dg = tid & 3;
        int t0 = 2 * tp, t1 = 2 * tp + 1;
        if (t0 > NTOK - 1) t0 = NTOK - 1;
        if (t1 > NTOK - 1) t1 = NTOK - 1;
        uint4 r0 = *(const uint4*)(base + (size_t)t0 * 768 + 512 + dg * 8);
        uint4 r1 = *(const uint4*)(base + (size_t)t1 * 768 + 512 + dg * 8);
        const __half* h0 = (const __half*)&r0;
        const __half* h1 = (const __half*)&r1;
#pragma unroll
        for (int i = 0; i < 8; i++) {
            __half2 w = __halves2half2(h0[i], h1[i]);
            svT[(dg * 8 + i) * 36 + tp] = *(uint32_t*)&w;
        }
    }
#pragma unroll
    for (int it = 0; it < 2; it++) {
        const int e = tid + it * 128;
        sp[(e >> 2) * 36 + 28 + (e & 3)] = 0;
    }
    svT[(tid >> 2) * 36 + 28 + (tid & 3)] = 0;
    __syncthreads();

    const int mtb = warp * 16;
    float sc[7][4];
#pragma unroll
    for (int nt = 0; nt < 7; nt++)
#pragma unroll
        for (int r = 0; r < 4; r++) sc[nt][r] = 0.f;

#pragma unroll
    for (int ko = 0; ko < 2; ko++) {
        const uint32_t a0 = sq[(mtb + g) * 36 + ko * 8 + t];
        const uint32_t a1 = sq[(mtb + g + 8) * 36 + ko * 8 + t];
        const uint32_t a2 = sq[(mtb + g) * 36 + ko * 8 + 4 + t];
        const uint32_t a3 = sq[(mtb + g + 8) * 36 + ko * 8 + 4 + t];
#pragma unroll
        for (int nt = 0; nt < 7; nt++) {
            const uint32_t b0 = sk[(nt * 8 + g) * 36 + ko * 8 + t];
            const uint32_t b1 = sk[(nt * 8 + g) * 36 + ko * 8 + 4 + t];
            asm volatile(
                "mma.sync.aligned.m16n8k16.row.col.f32.f16.f16.f32 "
                "{%0,%1,%2,%3}, {%4,%5,%6,%7}, {%8,%9}, {%0,%1,%2,%3};"
                : "+f"(sc[nt][0]), "+f"(sc[nt][1]), "+f"(sc[nt][2]), "+f"(sc[nt][3])
                : "r"(a0), "r"(a1), "r"(a2), "r"(a3), "r"(b0), "r"(b1));
        }
    }

    const int i0 = mtb + g, i1 = i0 + 8;
    const uint4* bp0 = (const uint4*)biasT + (((h * 64 + i0) * 4 + t) * 2);
    const uint4* bp1 = (const uint4*)biasT + (((h * 64 + i1) * 4 + t) * 2);
    uint4 wa0 = __ldg(bp0), wb0 = __ldg(bp0 + 1);
    uint4 wa1 = __ldg(bp1), wb1 = __ldg(bp1 + 1);
    const uint32_t bw0[8] = {wa0.x, wa0.y, wa0.z, wa0.w, wb0.x, wb0.y, wb0.z, wb0.w};
    const uint32_t bw1[8] = {wa1.x, wa1.y, wa1.z, wa1.w, wb1.x, wb1.y, wb1.z, wb1.w};

    float m0 = -1e30f, m1 = -1e30f;
#pragma unroll
    for (int nt = 0; nt < 7; nt++) {
        const float2 f0 = __half22float2(*(const __half2*)&bw0[nt]);
        const float2 f1 = __half22float2(*(const __half2*)&bw1[nt]);
        sc[nt][0] = fmaf(sc[nt][0], scale, f0.x);
        sc[nt][1] = fmaf(sc[nt][1], scale, f0.y);
        sc[nt][2] = fmaf(sc[nt][2], scale, f1.x);
        sc[nt][3] = fmaf(sc[nt][3], scale, f1.y);
        m0 = fmaxf(m0, fmaxf(sc[nt][0], sc[nt][1]));
        m1 = fmaxf(m1, fmaxf(sc[nt][2], sc[nt][3]));
    }
    m0 = fmaxf(m0, __shfl_xor_sync(0xffffffffu, m0, 1));
    m0 = fmaxf(m0, __shfl_xor_sync(0xffffffffu, m0, 2));
    m1 = fmaxf(m1, __shfl_xor_sync(0xffffffffu, m1, 1));
    m1 = fmaxf(m1, __shfl_xor_sync(0xffffffffu, m1, 2));

    float s0 = 0.f, s1 = 0.f;
#pragma unroll
    for (int nt = 0; nt < 7; nt++) {
        float p0 = __expf(sc[nt][0] - m0);
        float p1 = __expf(sc[nt][1] - m0);
        float p2 = __expf(sc[nt][2] - m1);
        float p3 = __expf(sc[nt][3] - m1);
        sc[nt][0] = p0; sc[nt][1] = p1; sc[nt][2] = p2; sc[nt][3] = p3;
        s0 += p0 + p1;
        s1 += p2 + p3;
    }
    s0 += __shfl_xor_sync(0xffffffffu, s0, 1);
    s0 += __shfl_xor_sync(0xffffffffu, s0, 2);
    s1 += __shfl_xor_sync(0xffffffffu, s1, 1);
    s1 += __shfl_xor_sync(0xffffffffu, s1, 2);
    const float inv0 = 1.f / s0, inv1 = 1.f / s1;

#pragma unroll
    for (int nt = 0; nt < 7; nt++) {
        sp[i0 * 36 + nt * 4 + t] = pack_h2(sc[nt][0], sc[nt][1]);
        sp[i1 * 36 + nt * 4 + t] = pack_h2(sc[nt][2], sc[nt][3]);
    }
    __syncwarp();

    float ov[4][4];
#pragma unroll
    for (int nt = 0; nt < 4; nt++)
#pragma unroll
        for (int r = 0; r < 4; r++) ov[nt][r] = 0.f;

#pragma unroll
    for (int ko = 0; ko < 4; ko++) {
        const uint32_t a0 = sp[(mtb + g) * 36 + ko * 8 + t];
        const uint32_t a1 = sp[(mtb + g + 8) * 36 + ko * 8 + t];
        const uint32_t a2 = sp[(mtb + g) * 36 + ko * 8 + 4 + t];
        const uint32_t a3 = sp[(mtb + g + 8) * 36 + ko * 8 + 4 + t];
#pragma unroll
        for (int nt = 0; nt < 4; nt++) {
            const uint32_t b0 = svT[(nt * 8 + g) * 36 + ko * 8 + t];
            const uint32_t b1 = svT[(nt * 8 + g) * 36 + ko * 8 + 4 + t];
            asm volatile(
                "mma.sync.aligned.m16n8k16.row.col.f32.f16.f16.f32 "
                "{%0,%1,%2,%3}, {%4,%5,%6,%7}, {%8,%9}, {%0,%1,%2,%3};"
                : "+f"(ov[nt][0]), "+f"(ov[nt][1]), "+f"(ov[nt][2]), "+f"(ov[nt][3])
                : "r"(a0), "r"(a1), "r"(a2), "r"(a3), "r"(b0), "r"(b1));
        }
    }

    const bool v0 = i0 < NTOK, v1 = i1 < NTOK;
#pragma unroll
    for (int nt = 0; nt < 4; nt++) {
        const int col = h * 32 + nt * 8 + 2 * t;
        if (v0) {
            *(__half2*)(out + ((size_t)b * NTOK + i0) * CDIM + col) =
                __floats2half2_rn(ov[nt][0] * inv0, ov[nt][1] * inv0);
        }
        if (v1) {
            *(__half2*)(out + ((size_t)b * NTOK + i1) * CDIM + col) =
                __floats2half2_rn(ov[nt][2] * inv1, ov[nt][3] * inv1);
        }
    }
}

// ---------------------------------------------------------------------------
// Launch
// ---------------------------------------------------------------------------
extern "C" void kernel_launch(void* const* d_in, const int* in_sizes, int n_in,
                              void* d_out, int out_size)
{
    const float* x      = (const float*)d_in[0];
    const float* qkv_w  = (const float*)d_in[1];
    const float* qkv_b  = (const float*)d_in[2];
    const float* rpb    = (const float*)d_in[3];
    const float* proj_w = (const float*)d_in[4];
    const float* proj_b = (const float*)d_in[5];
    float* out = (float*)d_out;

    __half* qkvh = nullptr;
    __half* atth = nullptr;
    uint32_t* wqkv = nullptr;
    uint32_t* wproj = nullptr;
    uint32_t* biasT = nullptr;
    cudaGetSymbolAddress((void**)&qkvh, g_qkv);
    cudaGetSymbolAddress((void**)&atth, g_att);
    cudaGetSymbolAddress((void**)&wqkv, g_wqkv);
    cudaGetSymbolAddress((void**)&wproj, g_wproj);
    cudaGetSymbolAddress((void**)&biasT, g_bias);

    constexpr int SMEM = 16384 * 4;   // 64 KB (A fragment image)
    cudaFuncSetAttribute(h16_gemm<float, __half, 768>,
                         cudaFuncAttributeMaxDynamicSharedMemorySize, SMEM);
    cudaFuncSetAttribute(h16_gemm<__half, float, 256>,
                         cudaFuncAttributeMaxDynamicSharedMemorySize, SMEM);

    // 0) one-time conversions (tiny)
    convert_w<<<384, 256>>>(qkv_w, wqkv, 768);
    convert_w<<<128, 256>>>(proj_w, wproj, 256);
    build_bias<<<64, 256>>>(rpb, biasT);

    // 1) QKV GEMM (barrier-free, LDG.128 B, fp16 out)
    h16_gemm<float, __half, 768><<<MROWS / 128, 128, SMEM>>>(x, wqkv, qkv_b, qkvh);

    // 2) Windowed attention
    {
        dim3 grid(BWIN, NHEAD);
        window_attn_h16<<<grid, 128>>>(qkvh, biasT, atth);
    }

    // 3) Projection GEMM (barrier-free, LDG.128 B, fp32 out)
    h16_gemm<__half, float, 256><<<MROWS / 128, 128, SMEM>>>(atth, wproj, proj_b, out);
}

// round 14
// speedup vs baseline: 1.3741x; 1.3741x over previous
#include <cuda_runtime.h>
#include <cuda_fp16.h>
#include <cstdint>

// Problem constants (fixed by setup_inputs)
#define BWIN   4096
#define NTOK   49
#define CDIM   256
#define NHEAD  8
#define MROWS  (BWIN * NTOK)   // 200704

// ---------------------------------------------------------------------------
// Scratch (device globals; no runtime allocation allowed)
// ---------------------------------------------------------------------------
__device__ __half   g_qkv[(size_t)MROWS * 768];
__device__ __half   g_att[(size_t)MROWS * CDIM];
__device__ uint32_t g_wqkv[6 * 16 * 32 * 32];        // word-major frag fp16 words
__device__ uint32_t g_wproj[2 * 16 * 32 * 32];
__device__ uint32_t g_bias[NHEAD * 64 * 32];         // [h][i][t][8] half2 words

__device__ __forceinline__ uint32_t pack_h2(float a, float b) {
    __half2 h = __floats2half2_rn(a, b);
    return *(uint32_t*)&h;
}

// ---------------------------------------------------------------------------
// Weight conversion: fp32 W[K,N] -> word-major fragment words (COALESCED:
// for a fixed word id, the 32 lanes are contiguous in memory):
//   dst[((nblk*16 + kc)*32 + w)*32 + lane],  w = wn*8 + nt*2 + reg
//   lane = g*4 + t;  n = nblk*128 + wn*32 + nt*8 + g;  k = kc*16 + reg*8 + t*2
//   word = half2(W[k][n], W[k+1][n])
// GEMM warp (wn) reads words w = wn*8 .. wn*8+7 per kc: 8x coalesced LDG.32.
// ---------------------------------------------------------------------------
__global__ void convert_w(const float* __restrict__ w, uint32_t* __restrict__ dst, int N)
{
    const int idx  = blockIdx.x * 256 + threadIdx.x;
    const int lane = idx & 31;
    const int wrd  = (idx >> 5) & 31;
    const int kc   = (idx >> 10) & 15;
    const int nblk = idx >> 14;
    const int wn  = wrd >> 3;          // 0..3 (32-col quarter)
    const int nt  = (wrd >> 1) & 3;    // 0..3
    const int reg = wrd & 1;
    const int g = lane >> 2, t = lane & 3;
    const int n = nblk * 128 + wn * 32 + nt * 8 + g;
    const int k = kc * 16 + reg * 8 + t * 2;
    dst[idx] = pack_h2(w[(size_t)k * N + n], w[(size_t)(k + 1) * N + n]);
}

// ---------------------------------------------------------------------------
// Bias+mask table: g_bias[((h*64+i)*4 + t)*8 + nt] = half2(B(i,j), B(i,j+1))
// ---------------------------------------------------------------------------
__global__ void build_bias(const float* __restrict__ rpb, uint32_t* __restrict__ dst)
{
    const int idx = blockIdx.x * 256 + threadIdx.x;
    const int nt = idx & 7;
    const int t  = (idx >> 3) & 3;
    const int i  = (idx >> 5) & 63;
    const int h  = idx >> 11;
    const int j0 = nt * 8 + 2 * t;
    float v[2];
#pragma unroll
    for (int e = 0; e < 2; e++) {
        const int j = j0 + e;
        if (i < NTOK && j < NTOK && nt < 7) {
            const int xi = i / 7, yi = i - xi * 7;
            const int xj = j / 7, yj = j - xj * 7;
            v[e] = rpb[((xi - xj + 6) * 13 + (yi - yj + 6)) * 8 + h];
        } else {
            v[e] = -10000.0f;
        }
    }
    dst[idx] = pack_h2(v[0], v[1]);
}

// ---------------------------------------------------------------------------
// BARRIER-FREE A-resident fp16 GEMM, warp tile 64x32 (8 warps, BM=128).
// acc = 64 regs/thread (vs 128 in the 64x64 tile) -> ~110 total regs, no
// spills under __launch_bounds__(256,2); 16 warps/SM (4/SMSP) doubles the
// latency-hiding pool. A fragment image resident in 64KB smem (one sync);
// B frags via 8 coalesced LDG.32 per warp per kc from word-major layout.
// ---------------------------------------------------------------------------
template<typename TA, typename TC, int N>
__global__ __launch_bounds__(256, 2)
void h16_gemm(const TA* __restrict__ A, const uint32_t* __restrict__ Bw,
              const float* __restrict__ bias, TC* __restrict__ C)
{
    constexpr int K = 256, NT = 16, NBLK = N / 128;
    extern __shared__ uint32_t Asm[];     // 16 kc * 8 mt * 4 reg * 32 = 16384 words

    const int tid  = threadIdx.x;
    const int lane = tid & 31;
    const int warp = tid >> 5;
    const int wm   = warp & 1;            // m half (0..1)
    const int wn   = warp >> 1;           // n quarter (0..3)
    const int bm   = blockIdx.x * 128;

    // ---- A resident fill (once) ---------------------------------------------
    if constexpr (sizeof(TA) == 4) {
#pragma unroll
        for (int it = 0; it < 32; it++) {
            const int e = it * 256 + tid;          // 8192 float4 loads
            const int row = e >> 6, c4 = e & 63;
            const int k = c4 * 4;
            const int kc = k >> 4;
            const int reg = ((row >> 3) & 1) + ((k >> 3) & 1) * 2;
            const int t0 = (k & 7) >> 1;
            const int mt = (row >> 4);
            const int g = row & 7;
            float4 v = *(const float4*)((const float*)A + (size_t)(bm + row) * K + k);
            uint2 w;
            w.x = pack_h2(v.x, v.y);
            w.y = pack_h2(v.z, v.w);
            *(uint2*)&Asm[((kc * 8 + mt) * 4 + reg) * 32 + g * 4 + t0] = w;
        }
    } else {
#pragma unroll
        for (int it = 0; it < 16; it++) {
            const int e = it * 256 + tid;          // 4096 uint4 loads
            const int row = e >> 5, c8 = e & 31;
            const int k = c8 * 8;
            const int kc = k >> 4;
            const int reg = ((row >> 3) & 1) + ((k >> 3) & 1) * 2;
            const int mt = (row >> 4);
            const int g = row & 7;
            uint4 v = *(const uint4*)((const __half*)A + (size_t)(bm + row) * K + k);
            *(uint4*)&Asm[((kc * 8 + mt) * 4 + reg) * 32 + g * 4] = v;
        }
    }
    __syncthreads();    // the ONLY block-wide barrier

    float acc[4][4][4];   // [mt][nt][reg] -- 64 registers

    for (int nblk = 0; nblk < NBLK; nblk++) {
#pragma unroll
        for (int i = 0; i < 4; i++)
#pragma unroll
            for (int j = 0; j < 4; j++)
#pragma unroll
                for (int r = 0; r < 4; r++) acc[i][j][r] = 0.f;

        // this warp's B words: w = wn*8 + (0..7), coalesced per word
        const uint32_t* bp = Bw + (size_t)nblk * 16384 + (wn * 8) * 32 + lane;

#pragma unroll
        for (int kc = 0; kc < NT; kc++) {
            uint32_t bf[8];
            const uint32_t* bk = bp + kc * 1024;
#pragma unroll
            for (int j = 0; j < 8; j++) bf[j] = __ldg(bk + j * 32);

            uint32_t af[4][4];
#pragma unroll
            for (int mt = 0; mt < 4; mt++) {
                const int base = ((kc * 8 + wm * 4 + mt) * 4) * 32 + lane;
#pragma unroll
                for (int r = 0; r < 4; r++) af[mt][r] = Asm[base + r * 32];
            }
#pragma unroll
            for (int mt = 0; mt < 4; mt++) {
#pragma unroll
                for (int nt = 0; nt < 4; nt++) {
                    asm volatile(
                        "mma.sync.aligned.m16n8k16.row.col.f32.f16.f16.f32 "
                        "{%0,%1,%2,%3}, {%4,%5,%6,%7}, {%8,%9}, {%0,%1,%2,%3};"
                        : "+f"(acc[mt][nt][0]), "+f"(acc[mt][nt][1]),
                          "+f"(acc[mt][nt][2]), "+f"(acc[mt][nt][3])
                        : "r"(af[mt][0]), "r"(af[mt][1]), "r"(af[mt][2]), "r"(af[mt][3]),
                          "r"(bf[nt * 2]), "r"(bf[nt * 2 + 1]));
                }
            }
        }

        // epilogue: bias + store
        const int g = lane >> 2, tig = lane & 3;
#pragma unroll
        for (int mt = 0; mt < 4; mt++) {
            const int r0 = bm + wm * 64 + mt * 16 + g;
#pragma unroll
            for (int nt = 0; nt < 4; nt++) {
                const int col = nblk * 128 + wn * 32 + nt * 8 + tig * 2;
                const float b0 = __ldg(bias + col);
                const float b1 = __ldg(bias + col + 1);
                if constexpr (sizeof(TC) == 2) {
                    __half* cp = (__half*)C;
                    *(__half2*)(cp + (size_t)r0 * N + col) =
                        __floats2half2_rn(acc[mt][nt][0] + b0, acc[mt][nt][1] + b1);
                    *(__half2*)(cp + (size_t)(r0 + 8) * N + col) =
                        __floats2half2_rn(acc[mt][nt][2] + b0, acc[mt][nt][3] + b1);
                } else {
                    float* cp = (float*)C;
                    *(float2*)(cp + (size_t)r0 * N + col) =
                        make_float2(acc[mt][nt][0] + b0, acc[mt][nt][1] + b1);
                    *(float2*)(cp + (size_t)(r0 + 8) * N + col) =
                        make_float2(acc[mt][nt][2] + b0, acc[mt][nt][3] + b1);
                }
            }
        }
    }
}

// ---------------------------------------------------------------------------
// PURE fp16 tensor-core windowed attention (mma.sync), vectorized bias table.
// (unchanged from rounds 10-13)
// ---------------------------------------------------------------------------
__global__ __launch_bounds__(128)
void window_attn_h16(const __half* __restrict__ qkv,
                     const uint32_t* __restrict__ biasT,
                     __half* __restrict__ out)
{
    __shared__ uint32_t sq [64 * 36];
    __shared__ uint32_t sk [56 * 36];
    __shared__ uint32_t svT[32 * 36];
    __shared__ uint32_t sp [64 * 36];

    const int b = blockIdx.x;
    const int h = blockIdx.y;
    const int tid  = threadIdx.x;
    const int lane = tid & 31;
    const int warp = tid >> 5;
    const int g = lane >> 2;
    const int t = lane & 3;

    const float scale = 0.17677669529663687f;
    const __half* base = qkv + (size_t)b * NTOK * 768 + h * 32;

#pragma unroll
    for (int it = 0; it < 2; it++) {
        const int e = tid + it * 128;
        const int row = e >> 2, c = e & 3;
        const int sr = row < NTOK ? row : NTOK - 1;
        *(uint4*)&sq[row * 36 + c * 4] =
            *(const uint4*)(base + (size_t)sr * 768 + c * 8);
    }
#pragma unroll
    for (int it = 0; it < 2; it++) {
        const int e = tid + it * 128;
        if (e < 224) {
            const int row = e >> 2, c = e & 3;
            const int sr = row < NTOK ? row : NTOK - 1;
            *(uint4*)&sk[row * 36 + c * 4] =
                *(const uint4*)(base + (size_t)sr * 768 + 256 + c * 8);
        }
    }
    if (tid < 112) {
        const int tp = tid >> 2, dg = tid & 3;
        int t0 = 2 * tp, t1 = 2 * tp + 1;
        if (t0 > NTOK - 1) t0 = NTOK - 1;
        if (t1 > NTOK - 1) t1 = NTOK - 1;
        uint4 r0 = *(const uint4*)(base + (size_t)t0 * 768 + 512 + dg * 8);
        uint4 r1 = *(const uint4*)(base + (size_t)t1 * 768 + 512 + dg * 8);
        const __half* h0 = (const __half*)&r0;
        const __half* h1 = (const __half*)&r1;
#pragma unroll
        for (int i = 0; i < 8; i++) {
            __half2 w = __halves2half2(h0[i], h1[i]);
            svT[(dg * 8 + i) * 36 + tp] = *(uint32_t*)&w;
        }
    }
#pragma unroll
    for (int it = 0; it < 2; it++) {
        const int e = tid + it * 128;
        sp[(e >> 2) * 36 + 28 + (e & 3)] = 0;
    }
    svT[(tid >> 2) * 36 + 28 + (tid & 3)] = 0;
    __syncthreads();

    const int mtb = warp * 16;
    float sc[7][4];
#pragma unroll
    for (int nt = 0; nt < 7; nt++)
#pragma unroll
        for (int r = 0; r < 4; r++) sc[nt][r] = 0.f;

#pragma unroll
    for (int ko = 0; ko < 2; ko++) {
        const uint32_t a0 = sq[(mtb + g) * 36 + ko * 8 + t];
        const uint32_t a1 = sq[(mtb + g + 8) * 36 + ko * 8 + t];
        const uint32_t a2 = sq[(mtb + g) * 36 + ko * 8 + 4 + t];
        const uint32_t a3 = sq[(mtb + g + 8) * 36 + ko * 8 + 4 + t];
#pragma unroll
        for (int nt = 0; nt < 7; nt++) {
            const uint32_t b0 = sk[(nt * 8 + g) * 36 + ko * 8 + t];
            const uint32_t b1 = sk[(nt * 8 + g) * 36 + ko * 8 + 4 + t];
            asm volatile(
                "mma.sync.aligned.m16n8k16.row.col.f32.f16.f16.f32 "
                "{%0,%1,%2,%3}, {%4,%5,%6,%7}, {%8,%9}, {%0,%1,%2,%3};"
                : "+f"(sc[nt][0]), "+f"(sc[nt][1]), "+f"(sc[nt][2]), "+f"(sc[nt][3])
                : "r"(a0), "r"(a1), "r"(a2), "r"(a3), "r"(b0), "r"(b1));
        }
    }

    const int i0 = mtb + g, i1 = i0 + 8;
    const uint4* bp0 = (const uint4*)biasT + (((h * 64 + i0) * 4 + t) * 2);
    const uint4* bp1 = (const uint4*)biasT + (((h * 64 + i1) * 4 + t) * 2);
    uint4 wa0 = __ldg(bp0), wb0 = __ldg(bp0 + 1);
    uint4 wa1 = __ldg(bp1), wb1 = __ldg(bp1 + 1);
    const uint32_t bw0[8] = {wa0.x, wa0.y, wa0.z, wa0.w, wb0.x, wb0.y, wb0.z, wb0.w};
    const uint32_t bw1[8] = {wa1.x, wa1.y, wa1.z, wa1.w, wb1.x, wb1.y, wb1.z, wb1.w};

    float m0 = -1e30f, m1 = -1e30f;
#pragma unroll
    for (int nt = 0; nt < 7; nt++) {
        const float2 f0 = __half22float2(*(const __half2*)&bw0[nt]);
        const float2 f1 = __half22float2(*(const __half2*)&bw1[nt]);
        sc[nt][0] = fmaf(sc[nt][0], scale, f0.x);
        sc[nt][1] = fmaf(sc[nt][1], scale, f0.y);
        sc[nt][2] = fmaf(sc[nt][2], scale, f1.x);
        sc[nt][3] = fmaf(sc[nt][3], scale, f1.y);
        m0 = fmaxf(m0, fmaxf(sc[nt][0], sc[nt][1]));
        m1 = fmaxf(m1, fmaxf(sc[nt][2], sc[nt][3]));
    }
    m0 = fmaxf(m0, __shfl_xor_sync(0xffffffffu, m0, 1));
    m0 = fmaxf(m0, __shfl_xor_sync(0xffffffffu, m0, 2));
    m1 = fmaxf(m1, __shfl_xor_sync(0xffffffffu, m1, 1));
    m1 = fmaxf(m1, __shfl_xor_sync(0xffffffffu, m1, 2));

    float s0 = 0.f, s1 = 0.f;
#pragma unroll
    for (int nt = 0; nt < 7; nt++) {
        float p0 = __expf(sc[nt][0] - m0);
        float p1 = __expf(sc[nt][1] - m0);
        float p2 = __expf(sc[nt][2] - m1);
        float p3 = __expf(sc[nt][3] - m1);
        sc[nt][0] = p0; sc[nt][1] = p1; sc[nt][2] = p2; sc[nt][3] = p3;
        s0 += p0 + p1;
        s1 += p2 + p3;
    }
    s0 += __shfl_xor_sync(0xffffffffu, s0, 1);
    s0 += __shfl_xor_sync(0xffffffffu, s0, 2);
    s1 += __shfl_xor_sync(0xffffffffu, s1, 1);
    s1 += __shfl_xor_sync(0xffffffffu, s1, 2);
    const float inv0 = 1.f / s0, inv1 = 1.f / s1;

#pragma unroll
    for (int nt = 0; nt < 7; nt++) {
        sp[i0 * 36 + nt * 4 + t] = pack_h2(sc[nt][0], sc[nt][1]);
        sp[i1 * 36 + nt * 4 + t] = pack_h2(sc[nt][2], sc[nt][3]);
    }
    __syncwarp();

    float ov[4][4];
#pragma unroll
    for (int nt = 0; nt < 4; nt++)
#pragma unroll
        for (int r = 0; r < 4; r++) ov[nt][r] = 0.f;

#pragma unroll
    for (int ko = 0; ko < 4; ko++) {
        const uint32_t a0 = sp[(mtb + g) * 36 + ko * 8 + t];
        const uint32_t a1 = sp[(mtb + g + 8) * 36 + ko * 8 + t];
        const uint32_t a2 = sp[(mtb + g) * 36 + ko * 8 + 4 + t];
        const uint32_t a3 = sp[(mtb + g + 8) * 36 + ko * 8 + 4 + t];
#pragma unroll
        for (int nt = 0; nt < 4; nt++) {
            const uint32_t b0 = svT[(nt * 8 + g) * 36 + ko * 8 + t];
            const uint32_t b1 = svT[(nt * 8 + g) * 36 + ko * 8 + 4 + t];
            asm volatile(
                "mma.sync.aligned.m16n8k16.row.col.f32.f16.f16.f32 "
                "{%0,%1,%2,%3}, {%4,%5,%6,%7}, {%8,%9}, {%0,%1,%2,%3};"
                : "+f"(ov[nt][0]), "+f"(ov[nt][1]), "+f"(ov[nt][2]), "+f"(ov[nt][3])
                : "r"(a0), "r"(a1), "r"(a2), "r"(a3), "r"(b0), "r"(b1));
        }
    }

    const bool v0 = i0 < NTOK, v1 = i1 < NTOK;
#pragma unroll
    for (int nt = 0; nt < 4; nt++) {
        const int col = h * 32 + nt * 8 + 2 * t;
        if (v0) {
            *(__half2*)(out + ((size_t)b * NTOK + i0) * CDIM + col) =
                __floats2half2_rn(ov[nt][0] * inv0, ov[nt][1] * inv0);
        }
        if (v1) {
            *(__half2*)(out + ((size_t)b * NTOK + i1) * CDIM + col) =
                __floats2half2_rn(ov[nt][2] * inv1, ov[nt][3] * inv1);
        }
    }
}

// ---------------------------------------------------------------------------
// Launch
// ---------------------------------------------------------------------------
extern "C" void kernel_launch(void* const* d_in, const int* in_sizes, int n_in,
                              void* d_out, int out_size)
{
    const float* x      = (const float*)d_in[0];
    const float* qkv_w  = (const float*)d_in[1];
    const float* qkv_b  = (const float*)d_in[2];
    const float* rpb    = (const float*)d_in[3];
    const float* proj_w = (const float*)d_in[4];
    const float* proj_b = (const float*)d_in[5];
    float* out = (float*)d_out;

    __half* qkvh = nullptr;
    __half* atth = nullptr;
    uint32_t* wqkv = nullptr;
    uint32_t* wproj = nullptr;
    uint32_t* biasT = nullptr;
    cudaGetSymbolAddress((void**)&qkvh, g_qkv);
    cudaGetSymbolAddress((void**)&atth, g_att);
    cudaGetSymbolAddress((void**)&wqkv, g_wqkv);
    cudaGetSymbolAddress((void**)&wproj, g_wproj);
    cudaGetSymbolAddress((void**)&biasT, g_bias);

    constexpr int SMEM = 16384 * 4;   // 64 KB (A fragment image)
    cudaFuncSetAttribute(h16_gemm<float, __half, 768>,
                         cudaFuncAttributeMaxDynamicSharedMemorySize, SMEM);
    cudaFuncSetAttribute(h16_gemm<__half, float, 256>,
                         cudaFuncAttributeMaxDynamicSharedMemorySize, SMEM);

    // 0) one-time conversions (tiny)
    convert_w<<<384, 256>>>(qkv_w, wqkv, 768);
    convert_w<<<128, 256>>>(proj_w, wproj, 256);
    build_bias<<<64, 256>>>(rpb, biasT);

    // 1) QKV GEMM (barrier-free, 64x32 warp tile, fp16 out)
    h16_gemm<float, __half, 768><<<MROWS / 128, 256, SMEM>>>(x, wqkv, qkv_b, qkvh);

    // 2) Windowed attention
    {
        dim3 grid(BWIN, NHEAD);
        window_attn_h16<<<grid, 128>>>(qkvh, biasT, atth);
    }

    // 3) Projection GEMM (barrier-free, 64x32 warp tile, fp32 out)
    h16_gemm<__half, float, 256><<<MROWS / 128, 256, SMEM>>>(atth, wproj, proj_b, out);
}